// round 2
// baseline (speedup 1.0000x reference)
#include <cuda_runtime.h>
#include <math.h>

#define BB 2
#define LL 4096
#define DD 1024
#define DI 2048
#define HH 16
#define HD 128
#define NN 128
#define CS 256
#define NC 16
#define MC 256
#define NM 16
#define PROJ 8208
#define BL 8192
#define ALPHA 0.5f

// ---------------- scratch (static device globals; no allocation) ----------------
static __device__ float g_xn[(size_t)BL * DD];
static __device__ float g_proj[(size_t)BL * PROJ];
static __device__ float g_val[(size_t)BL * DI];
static __device__ float g_cum[(size_t)BB * HH * NC * CS];
static __device__ float g_T[(size_t)BB * HH * NC * HD * NN];
static __device__ float g_hst[(size_t)BB * HH * NC * HD * NN];
static __device__ float g_Yg[(size_t)BL * DI];
static __device__ float g_out[(size_t)BL * DD];
static __device__ float g_v[(size_t)BL * DD];
static __device__ float g_wk[(size_t)BL * DD];
static __device__ float g_rkg[(size_t)BL * DD];
static __device__ float g_vgw[(size_t)BL * DD];
static __device__ float g_U[(size_t)BB * NM * DD * DD];
static __device__ float g_Wst[(size_t)BB * NM * DD * DD];
static __device__ float g_P[(size_t)BB * NM * MC * MC];
static __device__ float g_reads[(size_t)BL * DD];

enum { EPI_STORE = 0, EPI_MASK = 1, EPI_ADD = 2, EPI_FINAL = 3 };

// ---------------- generic batched fp32 SGEMM: C[m,n] = sum_k A[m,k]*B[n,k] ------
// A[m,k] at A + m*sam + k*sak ; B[n,k] at B + n*sbn + k*sbk ; C row stride scm.
// 128x128 tile, K-step 8, 256 threads, 8x8 micro-tile. M must be multiple of 128.
__global__ void __launch_bounds__(256) sgemm_kernel(
    const float* __restrict__ A, const float* __restrict__ B, float* __restrict__ C,
    int M, int N, int K,
    long sam, long sak, long sbn, long sbk, long scm,
    long bsa, long bsb, long bsc,
    int epi, const float* __restrict__ aux1, const float* __restrict__ aux2,
    const float* __restrict__ decayp, float alpha)
{
    __shared__ float As[8][128];
    __shared__ float Bs[8][128];
    int bz = blockIdx.z;
    A += (long)bz * bsa; B += (long)bz * bsb; C += (long)bz * bsc;
    int m0 = blockIdx.y * 128, n0 = blockIdx.x * 128;
    int t = threadIdx.x;
    int tx = t & 15, ty = t >> 4;
    float acc[8][8];
#pragma unroll
    for (int r = 0; r < 8; r++)
#pragma unroll
        for (int c = 0; c < 8; c++) acc[r][c] = 0.f;

    for (int k0 = 0; k0 < K; k0 += 8) {
        // ---- load A tile -> As[k][m]
        if (sak == 1) {
            int m = t >> 1, kh = (t & 1) * 4;
            const float* p = A + (long)(m0 + m) * sam + (k0 + kh);
            float4 v = *(const float4*)p;
            As[kh + 0][m] = v.x; As[kh + 1][m] = v.y; As[kh + 2][m] = v.z; As[kh + 3][m] = v.w;
        } else {
#pragma unroll
            for (int i = 0; i < 4; i++) {
                int e = t + i * 256; int m = e & 127; int kk = e >> 7;
                As[kk][m] = A[(long)(m0 + m) * sam + (long)(k0 + kk) * sak];
            }
        }
        // ---- load B tile -> Bs[k][n]
        if (sbk == 1) {
            int n = t >> 1, kh = (t & 1) * 4;
            float4 v = make_float4(0.f, 0.f, 0.f, 0.f);
            if (n0 + n < N) v = *(const float4*)(B + (long)(n0 + n) * sbn + (k0 + kh));
            Bs[kh + 0][n] = v.x; Bs[kh + 1][n] = v.y; Bs[kh + 2][n] = v.z; Bs[kh + 3][n] = v.w;
        } else {
#pragma unroll
            for (int i = 0; i < 4; i++) {
                int e = t + i * 256; int n = e & 127; int kk = e >> 7;
                Bs[kk][n] = (n0 + n < N) ? B[(long)(n0 + n) * sbn + (long)(k0 + kk) * sbk] : 0.f;
            }
        }
        __syncthreads();
#pragma unroll
        for (int kk = 0; kk < 8; kk++) {
            float a[8], b[8];
#pragma unroll
            for (int r = 0; r < 8; r++) { a[r] = As[kk][ty * 8 + r]; b[r] = Bs[kk][tx * 8 + r]; }
#pragma unroll
            for (int r = 0; r < 8; r++)
#pragma unroll
                for (int c = 0; c < 8; c++) acc[r][c] += a[r] * b[c];
        }
        __syncthreads();
    }

    float lg = 0.f;
    if (epi == EPI_MASK) {
        float gamma = 1.f / (1.f + expf(-decayp[0]));
        lg = logf(gamma);
    }
#pragma unroll
    for (int r = 0; r < 8; r++) {
        int m = m0 + ty * 8 + r;
#pragma unroll
        for (int c = 0; c < 8; c++) {
            int n = n0 + tx * 8 + c;
            if (n < N) {
                long idx = (long)m * scm + n;
                float v = acc[r][c];
                if (epi == EPI_STORE) C[idx] = v;
                else if (epi == EPI_MASK) C[idx] = (m > n) ? v * expf((float)(m - 1 - n) * lg) : 0.f;
                else if (epi == EPI_ADD) C[idx] += v;
                else C[idx] = aux1[idx] + aux2[idx] + alpha * v;
            }
        }
    }
}

// ---------------- rmsnorm ----------------
__global__ void rmsnorm_kernel(const float* __restrict__ x, const float* __restrict__ w)
{
    int row = blockIdx.x;
    const float* xr = x + (long)row * DD;
    float s = 0.f;
    for (int i = threadIdx.x; i < DD; i += 256) { float v = xr[i]; s += v * v; }
    __shared__ float red[256];
    red[threadIdx.x] = s; __syncthreads();
    for (int o = 128; o > 0; o >>= 1) {
        if (threadIdx.x < o) red[threadIdx.x] += red[threadIdx.x + o];
        __syncthreads();
    }
    float r = rsqrtf(red[0] / (float)DD + 1e-6f);
    for (int i = threadIdx.x; i < DD; i += 256)
        g_xn[(long)row * DD + i] = xr[i] * r * w[i];
}

// ---------------- depthwise conv (K=4) + SiLU ----------------
__global__ void conv_silu_kernel(const float* __restrict__ cw, const float* __restrict__ cb)
{
    long idx = (long)blockIdx.x * 256 + threadIdx.x;
    if (idx >= (long)BL * DI) return;
    int c = (int)(idx % DI);
    long bl = idx / DI;
    int l = (int)(bl % LL);
    long b = bl / LL;
    float acc = cb[c];
#pragma unroll
    for (int k = 0; k < 4; k++) {
        int ls = l - 3 + k;
        if (ls >= 0) acc += cw[c * 4 + k] * g_proj[(b * LL + ls) * (long)PROJ + c];
    }
    g_val[idx] = acc / (1.f + expf(-acc));
}

// ---------------- per-chunk cumulative log-decay ----------------
__global__ void cum_kernel(const float* __restrict__ dt_bias, const float* __restrict__ A_log)
{
    int bid = blockIdx.x;               // (b*HH + h)*NC + c
    int c = bid % NC; int h = (bid / NC) % HH; int b = bid / (NC * HH);
    int t = threadIdx.x;
    long row = (long)b * LL + c * CS + t;
    float x = g_proj[row * (long)PROJ + 2 * DI + 2 * HH * NN + h] + dt_bias[h];
    float sp = (x > 20.f) ? x : log1pf(expf(x));
    float ld = -expf(A_log[h]) * sp;
    __shared__ float s[256];
    s[t] = ld; __syncthreads();
    for (int o = 1; o < 256; o <<= 1) {
        float v = (t >= o) ? s[t - o] : 0.f;
        __syncthreads();
        s[t] += v;
        __syncthreads();
    }
    g_cum[(long)bid * CS + t] = s[t];
}

// ---------------- SSD per-chunk state contribution T[d,n] = sum_l v*B*exp(cl-cum) --
__global__ void __launch_bounds__(256) ssd_T_kernel()
{
    int bid = blockIdx.x;               // (b*HH + h)*NC + c
    int c = bid % NC; int h = (bid / NC) % HH; int b = bid / (NC * HH);
    const float* cumc = g_cum + (long)bid * CS;
    __shared__ float vw[32][128];
    __shared__ float Bs[32][128];
    __shared__ float ew[CS];
    int t = threadIdx.x;
    float cl = cumc[CS - 1];
    for (int i = t; i < CS; i += 256) ew[i] = expf(cl - cumc[i]);
    __syncthreads();
    int tx = t & 15, ty = t >> 4;
    float acc[8][8];
#pragma unroll
    for (int r = 0; r < 8; r++)
#pragma unroll
        for (int cc = 0; cc < 8; cc++) acc[r][cc] = 0.f;
    long rowb = (long)b * LL + (long)c * CS;
    for (int k0 = 0; k0 < CS; k0 += 32) {
#pragma unroll
        for (int i = 0; i < 16; i++) {
            int e = t + i * 256; int kl = e >> 7; int j = e & 127;
            long row = rowb + k0 + kl;
            vw[kl][j] = g_val[row * (long)DI + h * HD + j] * ew[k0 + kl];
            Bs[kl][j] = g_proj[row * (long)PROJ + 2 * DI + h * NN + j];
        }
        __syncthreads();
#pragma unroll 8
        for (int kk = 0; kk < 32; kk++) {
            float a[8], bb[8];
#pragma unroll
            for (int r = 0; r < 8; r++) { a[r] = vw[kk][ty * 8 + r]; bb[r] = Bs[kk][tx * 8 + r]; }
#pragma unroll
            for (int r = 0; r < 8; r++)
#pragma unroll
                for (int cc = 0; cc < 8; cc++) acc[r][cc] += a[r] * bb[cc];
        }
        __syncthreads();
    }
    float* Tb = g_T + (long)bid * HD * NN;
#pragma unroll
    for (int r = 0; r < 8; r++)
#pragma unroll
        for (int cc = 0; cc < 8; cc++)
            Tb[(ty * 8 + r) * NN + tx * 8 + cc] = acc[r][cc];
}

// ---------------- SSD h-state recurrence (16 steps, elementwise) ----------------
__global__ void hscan_kernel()
{
    long i = (long)blockIdx.x * 256 + threadIdx.x;
    if (i >= (long)BB * HH * HD * NN) return;
    int dn = (int)(i % (HD * NN));
    long bh = i / (HD * NN);
    float hcur = 0.f;
    for (int c = 0; c < NC; c++) {
        long off = (bh * NC + c) * (long)(HD * NN) + dn;
        float Ac = expf(g_cum[(bh * NC + c) * CS + CS - 1]);
        g_hst[off] = hcur;
        hcur = Ac * hcur + g_T[off];
    }
}

// ---------------- SSD intra-chunk Y + state apply + D-skip + gating ----------------
// grid: ((b*HH+h)*NC+c)*4 + ltile, block 256, dynamic smem.
__global__ void __launch_bounds__(256) ssd_Y_kernel(const float* __restrict__ Dskip)
{
    extern __shared__ float sm[];
    float* CsT = sm;                 // [128][65]  (C transposed: [n][l])
    float* buf = CsT + 128 * 65;     // 8448 floats (BmT[n*65+m] | vm[j*132+d] | hs[j*132+d])
    float* Mt = buf + 8448;          // [64][65]
    float* cumsh = Mt + 64 * 65;     // [256]

    int bid = blockIdx.x;
    int lt = bid & 3;
    int bhc = bid >> 2;
    int c = bhc % NC; int bh = bhc / NC; int h = bh % HH; int b = bh / HH;
    int t = threadIdx.x, tx = t & 15, ty = t >> 4;
    const float* cumc = g_cum + (long)bhc * CS;
    for (int i = t; i < CS; i += 256) cumsh[i] = cumc[i];
    int l0 = lt * 64;
    long rowb = (long)b * LL + (long)c * CS;

#pragma unroll
    for (int i = 0; i < 32; i++) {
        int e = t + i * 256; int n = e & 127; int l = e >> 7;
        CsT[n * 65 + l] = g_proj[(rowb + l0 + l) * (long)PROJ + 2 * DI + HH * NN + h * NN + n];
    }
    __syncthreads();

    float acc[4][8];
#pragma unroll
    for (int r = 0; r < 4; r++)
#pragma unroll
        for (int cc = 0; cc < 8; cc++) acc[r][cc] = 0.f;

    for (int mt = 0; mt <= lt; mt++) {
        int m0 = mt * 64;
#pragma unroll
        for (int i = 0; i < 32; i++) {
            int e = t + i * 256; int n = e & 127; int m = e >> 7;
            buf[n * 65 + m] = g_proj[(rowb + m0 + m) * (long)PROJ + 2 * DI + h * NN + n];
        }
        __syncthreads();
        float am[4][4];
#pragma unroll
        for (int r = 0; r < 4; r++)
#pragma unroll
            for (int s = 0; s < 4; s++) am[r][s] = 0.f;
#pragma unroll 4
        for (int n = 0; n < 128; n++) {
            float a0[4], b0[4];
#pragma unroll
            for (int r = 0; r < 4; r++) { a0[r] = CsT[n * 65 + ty * 4 + r]; b0[r] = buf[n * 65 + tx * 4 + r]; }
#pragma unroll
            for (int r = 0; r < 4; r++)
#pragma unroll
                for (int s = 0; s < 4; s++) am[r][s] += a0[r] * b0[s];
        }
        __syncthreads();
#pragma unroll
        for (int r = 0; r < 4; r++)
#pragma unroll
            for (int s = 0; s < 4; s++) {
                int ll = ty * 4 + r, mm = tx * 4 + s;
                int gl = l0 + ll, gm = m0 + mm;
                Mt[ll * 65 + mm] = (gl >= gm) ? am[r][s] * expf(cumsh[gl] - cumsh[gm]) : 0.f;
            }
        __syncthreads();
#pragma unroll
        for (int i = 0; i < 32; i++) {
            int e = t + i * 256; int d = e & 127; int j = e >> 7;
            buf[j * 132 + d] = g_val[(rowb + m0 + j) * (long)DI + h * HD + d];
        }
        __syncthreads();
#pragma unroll 4
        for (int j = 0; j < 64; j++) {
            float a0[4], b0[8];
#pragma unroll
            for (int r = 0; r < 4; r++) a0[r] = Mt[(ty * 4 + r) * 65 + j];
#pragma unroll
            for (int cc = 0; cc < 8; cc++) b0[cc] = buf[j * 132 + tx * 8 + cc];
#pragma unroll
            for (int r = 0; r < 4; r++)
#pragma unroll
                for (int cc = 0; cc < 8; cc++) acc[r][cc] += a0[r] * b0[cc];
        }
        __syncthreads();
    }

    // + exp(cum[l]) * C @ h^T  (h entering this chunk)
    const float* hb = g_hst + (long)bhc * HD * NN;
    for (int nt = 0; nt < 8; nt++) {
        int n0 = nt * 16;
#pragma unroll
        for (int i = 0; i < 8; i++) {
            int e = t + i * 256; int j = e & 15; int d = e >> 4;
            buf[j * 132 + d] = hb[d * NN + n0 + j];
        }
        __syncthreads();
#pragma unroll
        for (int r = 0; r < 4; r++) {
            float el = expf(cumsh[l0 + ty * 4 + r]);
            float tmp[8];
#pragma unroll
            for (int cc = 0; cc < 8; cc++) tmp[cc] = 0.f;
#pragma unroll
            for (int j = 0; j < 16; j++) {
                float cv = CsT[(n0 + j) * 65 + ty * 4 + r];
#pragma unroll
                for (int cc = 0; cc < 8; cc++) tmp[cc] += cv * buf[j * 132 + tx * 8 + cc];
            }
#pragma unroll
            for (int cc = 0; cc < 8; cc++) acc[r][cc] += el * tmp[cc];
        }
        __syncthreads();
    }

    // + D_skip * v, then * silu(gate), store
#pragma unroll
    for (int r = 0; r < 4; r++) {
        int gl = l0 + ty * 4 + r;
        long grow = rowb + gl;
#pragma unroll
        for (int cc = 0; cc < 8; cc++) {
            int d = tx * 8 + cc;
            float vv = g_val[grow * (long)DI + h * HD + d];
            float y = acc[r][cc] + Dskip[h * HD + d] * vv;
            float g = g_proj[grow * (long)PROJ + DI + h * HD + d];
            g_Yg[grow * (long)DI + h * HD + d] = y * g / (1.f + expf(-g));
        }
    }
}

// ---------------- memory-module prep: wk shift, gp/gw pre-scales ----------------
__global__ void memprep_kernel(const float* __restrict__ decayp)
{
    long i = (long)blockIdx.x * 256 + threadIdx.x;
    if (i >= (long)BL * DD) return;
    long bl = i / DD;
    int l = (int)(bl % LL);
    float gamma = 1.f / (1.f + expf(-decayp[0]));
    float lg = logf(gamma);
    int tt = l % MC;
    g_wk[i] = (l == 0) ? 0.f : g_out[i - DD];
    g_rkg[i] = g_out[i] * expf((float)tt * lg);
    g_vgw[i] = g_v[i] * expf((float)(MC - 1 - tt) * lg);
}

// ---------------- W-state recurrence (16 steps, elementwise) ----------------
__global__ void wscan_kernel(const float* __restrict__ decayp)
{
    long i = (long)blockIdx.x * 256 + threadIdx.x;
    if (i >= (long)BB * DD * DD) return;
    long de = i % ((long)DD * DD);
    long b = i / ((long)DD * DD);
    float gamma = 1.f / (1.f + expf(-decayp[0]));
    float gmc = expf(256.f * logf(gamma));
    float w = 0.f;
    for (int c = 0; c < NM; c++) {
        long off = (b * NM + c) * (long)(DD * DD) + de;
        g_Wst[off] = w;
        w = gmc * w + g_U[off];
    }
}

// ---------------- host launcher ----------------
static float* symaddr(const void* s)
{
    void* p = nullptr;
    cudaGetSymbolAddress(&p, s);
    return (float*)p;
}

extern "C" void kernel_launch(void* const* d_in, const int* in_sizes, int n_in,
                              void* d_out, int out_size)
{
    const float* x = (const float*)d_in[0];
    const float* norm_w = (const float*)d_in[1];
    const float* w_in = (const float*)d_in[2];
    const float* conv_w = (const float*)d_in[3];
    const float* conv_b = (const float*)d_in[4];
    const float* A_log = (const float*)d_in[5];
    const float* dt_bias = (const float*)d_in[6];
    const float* D_skip = (const float*)d_in[7];
    const float* w_out = (const float*)d_in[8];
    const float* w_write = (const float*)d_in[9];
    const float* w_read = (const float*)d_in[10];
    const float* decay = (const float*)d_in[11];
    float* out = (float*)d_out;

    float* p_xn = symaddr(g_xn);
    float* p_proj = symaddr(g_proj);
    float* p_Yg = symaddr(g_Yg);
    float* p_out = symaddr(g_out);
    float* p_v = symaddr(g_v);
    float* p_wk = symaddr(g_wk);
    float* p_rkg = symaddr(g_rkg);
    float* p_vgw = symaddr(g_vgw);
    float* p_U = symaddr(g_U);
    float* p_Wst = symaddr(g_Wst);
    float* p_P = symaddr(g_P);
    float* p_reads = symaddr(g_reads);

    const int ysmem = (128 * 65 + 8448 + 64 * 65 + 256) * 4;
    cudaFuncSetAttribute(ssd_Y_kernel, cudaFuncAttributeMaxDynamicSharedMemorySize, ysmem);

    // 1. rmsnorm
    rmsnorm_kernel<<<BL, 256>>>(x, norm_w);
    // 2. proj = xn @ w_in^T   [8192 x 8208 x 1024]
    sgemm_kernel<<<dim3((PROJ + 127) / 128, BL / 128, 1), 256>>>(
        p_xn, w_in, p_proj, BL, PROJ, DD,
        DD, 1, DD, 1, PROJ, 0, 0, 0, EPI_STORE, nullptr, nullptr, nullptr, 0.f);
    // 3. conv + silu
    conv_silu_kernel<<<(int)(((long)BL * DI + 255) / 256), 256>>>(conv_w, conv_b);
    // 4. chunk cumsum of log-decay
    cum_kernel<<<BB * HH * NC, 256>>>(dt_bias, A_log);
    // 5. per-chunk state outer products T
    ssd_T_kernel<<<BB * HH * NC, 256>>>();
    // 6. h-state recurrence
    hscan_kernel<<<(int)(((long)BB * HH * HD * NN + 255) / 256), 256>>>();
    // 7. intra-chunk Y + state apply + gating
    ssd_Y_kernel<<<BB * HH * NC * 4, 256, ysmem>>>(D_skip);
    // 8. out = Yg @ w_out^T
    sgemm_kernel<<<dim3(DD / 128, BL / 128, 1), 256>>>(
        p_Yg, w_out, p_out, BL, DD, DI,
        DI, 1, DI, 1, DD, 0, 0, 0, EPI_STORE, nullptr, nullptr, nullptr, 0.f);
    // 9. v = out @ w_write^T
    sgemm_kernel<<<dim3(DD / 128, BL / 128, 1), 256>>>(
        p_out, w_write, p_v, BL, DD, DD,
        DD, 1, DD, 1, DD, 0, 0, 0, EPI_STORE, nullptr, nullptr, nullptr, 0.f);
    // 10. wk shift + pre-scales
    memprep_kernel<<<(int)(((long)BL * DD + 255) / 256), 256>>>(decay);
    // 11. U[b,c,d,e] = sum_t vgw[t,d] * wk[t,e]   (batched 32)
    sgemm_kernel<<<dim3(DD / 128, DD / 128, BB * NM), 256>>>(
        p_vgw, p_wk, p_U, DD, DD, MC,
        1, DD, 1, DD, DD,
        (long)MC * DD, (long)MC * DD, (long)DD * DD,
        EPI_STORE, nullptr, nullptr, nullptr, 0.f);
    // 12. W-state recurrence
    wscan_kernel<<<(int)(((long)BB * DD * DD + 255) / 256), 256>>>(decay);
    // 13. inter: reads = rkg @ Wst^T   (batched 32)
    sgemm_kernel<<<dim3(DD / 128, MC / 128, BB * NM), 256>>>(
        p_rkg, p_Wst, p_reads, MC, DD, DD,
        DD, 1, DD, 1, DD,
        (long)MC * DD, (long)DD * DD, (long)MC * DD,
        EPI_STORE, nullptr, nullptr, nullptr, 0.f);
    // 14. P = (rk @ wk^T) * Mmem  (decay-masked, batched 32)
    sgemm_kernel<<<dim3(MC / 128, MC / 128, BB * NM), 256>>>(
        p_out, p_wk, p_P, MC, MC, DD,
        DD, 1, DD, 1, MC,
        (long)MC * DD, (long)MC * DD, (long)MC * MC,
        EPI_MASK, nullptr, nullptr, decay, 0.f);
    // 15. reads += P @ v  (batched 32)
    sgemm_kernel<<<dim3(DD / 128, MC / 128, BB * NM), 256>>>(
        p_P, p_v, p_reads, MC, DD, MC,
        MC, 1, 1, DD, DD,
        (long)MC * MC, (long)MC * DD, (long)MC * DD,
        EPI_ADD, nullptr, nullptr, nullptr, 0.f);
    // 16. final = x + out + 0.5 * reads @ w_read^T
    sgemm_kernel<<<dim3(DD / 128, BL / 128, 1), 256>>>(
        p_reads, w_read, out, BL, DD, DD,
        DD, 1, DD, 1, DD, 0, 0, 0,
        EPI_FINAL, x, p_out, nullptr, ALPHA);
}

// round 5
// speedup vs baseline: 2.0853x; 2.0853x over previous
#include <cuda_runtime.h>
#include <cuda_bf16.h>
#include <math.h>
#include <stdint.h>

#define BB 2
#define LL 4096
#define DD 1024
#define DI 2048
#define HH 16
#define HD 128
#define NN 128
#define CS 256
#define NC 16
#define MC 256
#define NM 16
#define PROJ 8208
#define BL 8192
#define ALPHA 0.5f

// ================= fp32 scratch =================
static __device__ __align__(256) float g_proj[(size_t)BL * PROJ];
static __device__ __align__(256) float g_val[(size_t)BL * DI];
static __device__ __align__(256) float g_cum[(size_t)BB * HH * NC * CS];
static __device__ __align__(256) float g_T[(size_t)BB * HH * NC * HD * NN];
static __device__ __align__(256) float g_hst[(size_t)BB * HH * NC * HD * NN];
static __device__ __align__(256) float g_out[(size_t)BL * DD];
static __device__ __align__(256) float g_v[(size_t)BL * DD];
static __device__ __align__(256) float g_vgw[(size_t)BL * DD];
static __device__ __align__(256) float g_U[(size_t)BB * NM * DD * DD];
static __device__ __align__(256) float g_reads[(size_t)BL * DD];

// ================= bf16 split scratch =================
static __device__ __align__(256) __nv_bfloat16 g_xnh[(size_t)BL * DD],    g_xnl[(size_t)BL * DD];
static __device__ __align__(256) __nv_bfloat16 g_winh[(size_t)PROJ * DD], g_winl[(size_t)PROJ * DD];
static __device__ __align__(256) __nv_bfloat16 g_Ygh[(size_t)BL * DI],    g_Ygl[(size_t)BL * DI];
static __device__ __align__(256) __nv_bfloat16 g_woh[(size_t)DD * DI],    g_wol[(size_t)DD * DI];
static __device__ __align__(256) __nv_bfloat16 g_outh[(size_t)BL * DD],   g_outl[(size_t)BL * DD];
static __device__ __align__(256) __nv_bfloat16 g_wwh[(size_t)DD * DD],    g_wwl[(size_t)DD * DD];
static __device__ __align__(256) __nv_bfloat16 g_wrh[(size_t)DD * DD],    g_wrl[(size_t)DD * DD];
static __device__ __align__(256) __nv_bfloat16 g_wkh[(size_t)BL * DD],    g_wkl[(size_t)BL * DD];
static __device__ __align__(256) __nv_bfloat16 g_wkTh[(size_t)BL * DD],   g_wkTl[(size_t)BL * DD];
static __device__ __align__(256) __nv_bfloat16 g_rkgh[(size_t)BL * DD],   g_rkgl[(size_t)BL * DD];
static __device__ __align__(256) __nv_bfloat16 g_vgwTh[(size_t)BL * DD],  g_vgwTl[(size_t)BL * DD];
static __device__ __align__(256) __nv_bfloat16 g_vTh[(size_t)BL * DD],    g_vTl[(size_t)BL * DD];
static __device__ __align__(256) __nv_bfloat16 g_Wsth[(size_t)BB * NM * DD * DD], g_Wstl[(size_t)BB * NM * DD * DD];
static __device__ __align__(256) __nv_bfloat16 g_Ph[(size_t)BB * NM * MC * MC],   g_Pl[(size_t)BB * NM * MC * MC];
static __device__ __align__(256) __nv_bfloat16 g_rdh[(size_t)BL * DD],    g_rdl[(size_t)BL * DD];

enum { EPI_STORE = 0, EPI_MASK_SPLIT = 1, EPI_ADD = 2, EPI_FINAL = 3, EPI_STORE_SPLIT = 4 };

// ================= ptx helpers (all plain sm_80+ features) =================
__device__ __forceinline__ uint32_t smem_u32(const void* p) {
    uint32_t a;
    asm("{ .reg .u64 tmp; cvta.to.shared.u64 tmp, %1; cvt.u32.u64 %0, tmp; }" : "=r"(a) : "l"(p));
    return a;
}
__device__ __forceinline__ void cp16(uint32_t dst, const void* src, int ok) {
    int sz = ok ? 16 : 0;
    asm volatile("cp.async.cg.shared.global [%0], [%1], 16, %2;" :: "r"(dst), "l"(src), "r"(sz) : "memory");
}
#define CP_COMMIT() asm volatile("cp.async.commit_group;" ::: "memory")
#define CP_WAIT1()  asm volatile("cp.async.wait_group 1;" ::: "memory")
#define CP_WAIT0()  asm volatile("cp.async.wait_group 0;" ::: "memory")

#define LDM4(r, a) \
    asm volatile("ldmatrix.sync.aligned.m8n8.x4.shared.b16 {%0,%1,%2,%3}, [%4];" \
        : "=r"((r)[0]), "=r"((r)[1]), "=r"((r)[2]), "=r"((r)[3]) : "r"(a))
#define LDM2(r, a) \
    asm volatile("ldmatrix.sync.aligned.m8n8.x2.shared.b16 {%0,%1}, [%2];" \
        : "=r"((r)[0]), "=r"((r)[1]) : "r"(a))
#define MMA16816(c, a, b) \
    asm volatile("mma.sync.aligned.m16n8k16.row.col.f32.bf16.bf16.f32 " \
        "{%0,%1,%2,%3}, {%4,%5,%6,%7}, {%8,%9}, {%0,%1,%2,%3};" \
        : "+f"((c)[0]), "+f"((c)[1]), "+f"((c)[2]), "+f"((c)[3]) \
        : "r"((a)[0]), "r"((a)[1]), "r"((a)[2]), "r"((a)[3]), "r"((b)[0]), "r"((b)[1]))

__device__ __forceinline__ void split2(float v, __nv_bfloat16& h, __nv_bfloat16& l) {
    h = __float2bfloat16(v);
    l = __float2bfloat16(v - __bfloat162float(h));
}

// ================= mma.sync split-bf16 GEMM =================
// C[m,n] = sum_k A[m,k]*B[n,k], via Ahi*Bhi + Ahi*Blo + Alo*Bhi
// block tile 128x128, BK=32, 256 threads (8 warps, 2x4), warp tile 64x32.
// smem per stage: 4 tiles (Ah,Al,Bh,Bl), each 128 rows x 80B (32 bf16 + pad).
#define TILE_B 10240
#define STAGE_B 40960
__global__ void __launch_bounds__(256) tgemm_kernel(
    const __nv_bfloat16* __restrict__ Ahi, const __nv_bfloat16* __restrict__ Alo,
    const __nv_bfloat16* __restrict__ Bhi, const __nv_bfloat16* __restrict__ Blo,
    float* __restrict__ C, __nv_bfloat16* __restrict__ Chi, __nv_bfloat16* __restrict__ Clo,
    int N, int K, long lda, long ldb, long ldc,
    long bsa, long bsb, long bsc,
    int epi, const float* __restrict__ aux1, const float* __restrict__ aux2,
    const float* __restrict__ decayp, float alpha)
{
    extern __shared__ char smem[];
    uint32_t sbase = smem_u32(smem);
    int t = threadIdx.x, lane = t & 31, wid = t >> 5;
    int wm = wid >> 2, wn = wid & 3;

    int bz = blockIdx.z;
    Ahi += (long)bz * bsa; Alo += (long)bz * bsa;
    Bhi += (long)bz * bsb; Blo += (long)bz * bsb;
    long m0 = (long)blockIdx.y * 128, n0 = (long)blockIdx.x * 128;

    float acc[4][4][4];
#pragma unroll
    for (int mt = 0; mt < 4; mt++)
#pragma unroll
        for (int nt = 0; nt < 4; nt++)
#pragma unroll
            for (int e = 0; e < 4; e++) acc[mt][nt][e] = 0.f;

    int nk = K >> 5;  // K-chunks of 32

    // per-thread load assignment: 8 chunks of 16B per stage
    // chunk ch: tile=ch>>9, idx=ch&511, row=idx>>2, part=idx&3
    auto load_stage = [&](int s, int ck) {
        long k0 = (long)ck * 32;
        uint32_t sb = sbase + s * STAGE_B;
#pragma unroll
        for (int i = 0; i < 8; i++) {
            int ch = t + i * 256;
            int tile = ch >> 9; int idx = ch & 511; int row = idx >> 2; int part = idx & 3;
            uint32_t dst = sb + tile * TILE_B + row * 80 + part * 16;
            const __nv_bfloat16* srcp;
            int ok = 1;
            if (tile == 0)      srcp = Ahi + (m0 + row) * lda + k0 + part * 8;
            else if (tile == 1) srcp = Alo + (m0 + row) * lda + k0 + part * 8;
            else {
                ok = (n0 + row) < N;
                long r = ok ? (n0 + row) : 0;
                srcp = ((tile == 2) ? Bhi : Blo) + r * ldb + k0 + part * 8;
            }
            cp16(dst, srcp, ok);
        }
        CP_COMMIT();
    };

    load_stage(0, 0);

    for (int ck = 0; ck < nk; ck++) {
        int s = ck & 1;
        if (ck + 1 < nk) { load_stage(s ^ 1, ck + 1); CP_WAIT1(); }
        else CP_WAIT0();
        __syncthreads();

        uint32_t sb = sbase + s * STAGE_B;
        // A frag addr: row = wm*64 + mt*16 + lane%16 ; kcol = ks*16 + (lane/16)*8
        // B frag addr: row = wn*32 + nt*8 + lane%8  ; kcol = ks*16 + ((lane>>3)&1)*8
        uint32_t a_r = (uint32_t)(wm * 64 + (lane & 15));
        uint32_t a_kb = (uint32_t)((lane >> 4) * 16);  // bytes
        uint32_t b_r = (uint32_t)(wn * 32 + (lane & 7));
        uint32_t b_kb = (uint32_t)(((lane >> 3) & 1) * 16);
#pragma unroll
        for (int ks = 0; ks < 2; ks++) {
            uint32_t kof = ks * 32;  // bytes
            uint32_t bh[4][2], bl[4][2];
#pragma unroll
            for (int nt = 0; nt < 4; nt++) {
                uint32_t ab = sb + (b_r + nt * 8) * 80 + kof + b_kb;
                LDM2(bh[nt], ab + 2 * TILE_B);
                LDM2(bl[nt], ab + 3 * TILE_B);
            }
#pragma unroll
            for (int mt = 0; mt < 4; mt++) {
                uint32_t ah[4], al[4];
                uint32_t aa = sb + (a_r + mt * 16) * 80 + kof + a_kb;
                LDM4(ah, aa);
                LDM4(al, aa + TILE_B);
#pragma unroll
                for (int nt = 0; nt < 4; nt++) {
                    MMA16816(acc[mt][nt], ah, bh[nt]);
                    MMA16816(acc[mt][nt], ah, bl[nt]);
                    MMA16816(acc[mt][nt], al, bh[nt]);
                }
            }
        }
        __syncthreads();
    }

    // ---- epilogue: direct register -> global ----
    float lg = 0.f;
    if (epi == EPI_MASK_SPLIT) {
        float gamma = 1.f / (1.f + expf(-decayp[0]));
        lg = logf(gamma);
    }
    C += (long)bz * bsc;
    if (Chi) { Chi += (long)bz * bsc; Clo += (long)bz * bsc; }

#pragma unroll
    for (int mt = 0; mt < 4; mt++) {
#pragma unroll
        for (int nt = 0; nt < 4; nt++) {
            long col = n0 + wn * 32 + nt * 8 + (lane & 3) * 2;
            long row0 = m0 + wm * 64 + mt * 16 + (lane >> 2);
#pragma unroll
            for (int e = 0; e < 4; e++) {
                long m = row0 + (e >> 1) * 8;
                long n = col + (e & 1);
                if (n >= N) continue;
                long idx = m * ldc + n;
                float v = acc[mt][nt][e];
                if (epi == EPI_STORE) C[idx] = v;
                else if (epi == EPI_STORE_SPLIT) {
                    C[idx] = v;
                    split2(v, Chi[idx], Clo[idx]);
                } else if (epi == EPI_MASK_SPLIT) {
                    float mv = (m > n) ? v * expf((float)(m - 1 - n) * lg) : 0.f;
                    split2(mv, Chi[idx], Clo[idx]);
                } else if (epi == EPI_ADD) C[idx] += v;
                else C[idx] = aux1[idx] + aux2[idx] + alpha * v;
            }
        }
    }
}

// ================= elementwise / SIMT kernels =================
__global__ void splitk_kernel(const float* __restrict__ src, __nv_bfloat16* __restrict__ h,
                              __nv_bfloat16* __restrict__ l, long n)
{
    long i = (long)blockIdx.x * 256 + threadIdx.x;
    if (i >= n) return;
    split2(src[i], h[i], l[i]);
}

// transpose-split: dst[((b*NM+c)*DD+d)*MC+t] = src[(b*LL+c*MC+t)*DD+d] (shift: row-1, 0 at l==0)
__global__ void tsplit_kernel(const float* __restrict__ src, __nv_bfloat16* __restrict__ h,
                              __nv_bfloat16* __restrict__ l, int shift)
{
    long i = (long)blockIdx.x * 256 + threadIdx.x;
    if (i >= (long)BL * DD) return;
    int d = (int)(i % DD);
    long bl = i / DD;
    int linb = (int)(bl % LL);
    int t = linb % MC, cz = linb / MC;
    long b = bl / LL;
    float v;
    if (shift) v = (linb == 0) ? 0.f : src[i - DD];
    else v = src[i];
    long dst = (((long)b * NM + cz) * DD + d) * MC + t;
    split2(v, h[dst], l[dst]);
}

__global__ void rmsnorm_kernel(const float* __restrict__ x, const float* __restrict__ w)
{
    int row = blockIdx.x;
    const float* xr = x + (long)row * DD;
    float s = 0.f;
    for (int i = threadIdx.x; i < DD; i += 256) { float v = xr[i]; s += v * v; }
    __shared__ float red[256];
    red[threadIdx.x] = s; __syncthreads();
    for (int o = 128; o > 0; o >>= 1) {
        if (threadIdx.x < o) red[threadIdx.x] += red[threadIdx.x + o];
        __syncthreads();
    }
    float r = rsqrtf(red[0] / (float)DD + 1e-6f);
    for (int i = threadIdx.x; i < DD; i += 256) {
        float v = xr[i] * r * w[i];
        long idx = (long)row * DD + i;
        split2(v, g_xnh[idx], g_xnl[idx]);
    }
}

__global__ void conv_silu_kernel(const float* __restrict__ cw, const float* __restrict__ cb)
{
    long idx = (long)blockIdx.x * 256 + threadIdx.x;
    if (idx >= (long)BL * DI) return;
    int c = (int)(idx % DI);
    long bl = idx / DI;
    int l = (int)(bl % LL);
    long b = bl / LL;
    float acc = cb[c];
#pragma unroll
    for (int k = 0; k < 4; k++) {
        int ls = l - 3 + k;
        if (ls >= 0) acc += cw[c * 4 + k] * g_proj[(b * LL + ls) * (long)PROJ + c];
    }
    g_val[idx] = acc / (1.f + expf(-acc));
}

__global__ void cum_kernel(const float* __restrict__ dt_bias, const float* __restrict__ A_log)
{
    int bid = blockIdx.x;
    int c = bid % NC; int h = (bid / NC) % HH; int b = bid / (NC * HH);
    int t = threadIdx.x;
    long row = (long)b * LL + c * CS + t;
    float x = g_proj[row * (long)PROJ + 2 * DI + 2 * HH * NN + h] + dt_bias[h];
    float sp = (x > 20.f) ? x : log1pf(expf(x));
    float ld = -expf(A_log[h]) * sp;
    __shared__ float s[256];
    s[t] = ld; __syncthreads();
    for (int o = 1; o < 256; o <<= 1) {
        float v = (t >= o) ? s[t - o] : 0.f;
        __syncthreads();
        s[t] += v;
        __syncthreads();
    }
    g_cum[(long)bid * CS + t] = s[t];
}

__global__ void __launch_bounds__(256) ssd_T_kernel()
{
    int bid = blockIdx.x;
    int c = bid % NC; int h = (bid / NC) % HH; int b = bid / (NC * HH);
    const float* cumc = g_cum + (long)bid * CS;
    __shared__ float vw[32][128];
    __shared__ float Bs[32][128];
    __shared__ float ew[CS];
    int t = threadIdx.x;
    float cl = cumc[CS - 1];
    for (int i = t; i < CS; i += 256) ew[i] = expf(cl - cumc[i]);
    __syncthreads();
    int tx = t & 15, ty = t >> 4;
    float acc[8][8];
#pragma unroll
    for (int r = 0; r < 8; r++)
#pragma unroll
        for (int cc = 0; cc < 8; cc++) acc[r][cc] = 0.f;
    long rowb = (long)b * LL + (long)c * CS;
    for (int k0 = 0; k0 < CS; k0 += 32) {
#pragma unroll
        for (int i = 0; i < 16; i++) {
            int e = t + i * 256; int kl = e >> 7; int j = e & 127;
            long row = rowb + k0 + kl;
            vw[kl][j] = g_val[row * (long)DI + h * HD + j] * ew[k0 + kl];
            Bs[kl][j] = g_proj[row * (long)PROJ + 2 * DI + h * NN + j];
        }
        __syncthreads();
#pragma unroll 8
        for (int kk = 0; kk < 32; kk++) {
            float a[8], bb[8];
#pragma unroll
            for (int r = 0; r < 8; r++) { a[r] = vw[kk][ty * 8 + r]; bb[r] = Bs[kk][tx * 8 + r]; }
#pragma unroll
            for (int r = 0; r < 8; r++)
#pragma unroll
                for (int cc = 0; cc < 8; cc++) acc[r][cc] += a[r] * bb[cc];
        }
        __syncthreads();
    }
    float* Tb = g_T + (long)bid * HD * NN;
#pragma unroll
    for (int r = 0; r < 8; r++)
#pragma unroll
        for (int cc = 0; cc < 8; cc++)
            Tb[(ty * 8 + r) * NN + tx * 8 + cc] = acc[r][cc];
}

__global__ void hscan_kernel()
{
    long i = (long)blockIdx.x * 256 + threadIdx.x;
    if (i >= (long)BB * HH * HD * NN) return;
    int dn = (int)(i % (HD * NN));
    long bh = i / (HD * NN);
    float hcur = 0.f;
    for (int c = 0; c < NC; c++) {
        long off = (bh * NC + c) * (long)(HD * NN) + dn;
        float Ac = expf(g_cum[(bh * NC + c) * CS + CS - 1]);
        g_hst[off] = hcur;
        hcur = Ac * hcur + g_T[off];
    }
}

__global__ void __launch_bounds__(256) ssd_Y_kernel(const float* __restrict__ Dskip)
{
    extern __shared__ float sm[];
    float* CsT = sm;
    float* buf = CsT + 128 * 65;
    float* Mt = buf + 8448;
    float* cumsh = Mt + 64 * 65;

    int bid = blockIdx.x;
    int lt = bid & 3;
    int bhc = bid >> 2;
    int c = bhc % NC; int bh = bhc / NC; int h = bh % HH; int b = bh / HH;
    int t = threadIdx.x, tx = t & 15, ty = t >> 4;
    const float* cumc = g_cum + (long)bhc * CS;
    for (int i = t; i < CS; i += 256) cumsh[i] = cumc[i];
    int l0 = lt * 64;
    long rowb = (long)b * LL + (long)c * CS;

#pragma unroll
    for (int i = 0; i < 32; i++) {
        int e = t + i * 256; int n = e & 127; int l = e >> 7;
        CsT[n * 65 + l] = g_proj[(rowb + l0 + l) * (long)PROJ + 2 * DI + HH * NN + h * NN + n];
    }
    __syncthreads();

    float acc[4][8];
#pragma unroll
    for (int r = 0; r < 4; r++)
#pragma unroll
        for (int cc = 0; cc < 8; cc++) acc[r][cc] = 0.f;

    for (int mt = 0; mt <= lt; mt++) {
        int m0 = mt * 64;
#pragma unroll
        for (int i = 0; i < 32; i++) {
            int e = t + i * 256; int n = e & 127; int m = e >> 7;
            buf[n * 65 + m] = g_proj[(rowb + m0 + m) * (long)PROJ + 2 * DI + h * NN + n];
        }
        __syncthreads();
        float am[4][4];
#pragma unroll
        for (int r = 0; r < 4; r++)
#pragma unroll
            for (int s = 0; s < 4; s++) am[r][s] = 0.f;
#pragma unroll 4
        for (int n = 0; n < 128; n++) {
            float a0[4], b0[4];
#pragma unroll
            for (int r = 0; r < 4; r++) { a0[r] = CsT[n * 65 + ty * 4 + r]; b0[r] = buf[n * 65 + tx * 4 + r]; }
#pragma unroll
            for (int r = 0; r < 4; r++)
#pragma unroll
                for (int s = 0; s < 4; s++) am[r][s] += a0[r] * b0[s];
        }
        __syncthreads();
#pragma unroll
        for (int r = 0; r < 4; r++)
#pragma unroll
            for (int s = 0; s < 4; s++) {
                int ll = ty * 4 + r, mm = tx * 4 + s;
                int gl = l0 + ll, gm = m0 + mm;
                Mt[ll * 65 + mm] = (gl >= gm) ? am[r][s] * expf(cumsh[gl] - cumsh[gm]) : 0.f;
            }
        __syncthreads();
#pragma unroll
        for (int i = 0; i < 32; i++) {
            int e = t + i * 256; int d = e & 127; int j = e >> 7;
            buf[j * 132 + d] = g_val[(rowb + m0 + j) * (long)DI + h * HD + d];
        }
        __syncthreads();
#pragma unroll 4
        for (int j = 0; j < 64; j++) {
            float a0[4], b0[8];
#pragma unroll
            for (int r = 0; r < 4; r++) a0[r] = Mt[(ty * 4 + r) * 65 + j];
#pragma unroll
            for (int cc = 0; cc < 8; cc++) b0[cc] = buf[j * 132 + tx * 8 + cc];
#pragma unroll
            for (int r = 0; r < 4; r++)
#pragma unroll
                for (int cc = 0; cc < 8; cc++) acc[r][cc] += a0[r] * b0[cc];
        }
        __syncthreads();
    }

    const float* hb = g_hst + (long)bhc * HD * NN;
    for (int nt = 0; nt < 8; nt++) {
        int n0 = nt * 16;
#pragma unroll
        for (int i = 0; i < 8; i++) {
            int e = t + i * 256; int j = e & 15; int d = e >> 4;
            buf[j * 132 + d] = hb[d * NN + n0 + j];
        }
        __syncthreads();
#pragma unroll
        for (int r = 0; r < 4; r++) {
            float el = expf(cumsh[l0 + ty * 4 + r]);
            float tmp[8];
#pragma unroll
            for (int cc = 0; cc < 8; cc++) tmp[cc] = 0.f;
#pragma unroll
            for (int j = 0; j < 16; j++) {
                float cv = CsT[(n0 + j) * 65 + ty * 4 + r];
#pragma unroll
                for (int cc = 0; cc < 8; cc++) tmp[cc] += cv * buf[j * 132 + tx * 8 + cc];
            }
#pragma unroll
            for (int cc = 0; cc < 8; cc++) acc[r][cc] += el * tmp[cc];
        }
        __syncthreads();
    }

#pragma unroll
    for (int r = 0; r < 4; r++) {
        int gl = l0 + ty * 4 + r;
        long grow = rowb + gl;
#pragma unroll
        for (int cc = 0; cc < 8; cc++) {
            int d = tx * 8 + cc;
            float vv = g_val[grow * (long)DI + h * HD + d];
            float y = acc[r][cc] + Dskip[h * HD + d] * vv;
            float g = g_proj[grow * (long)PROJ + DI + h * HD + d];
            float yo = y * g / (1.f + expf(-g));
            long idx = grow * (long)DI + h * HD + d;
            split2(yo, g_Ygh[idx], g_Ygl[idx]);
        }
    }
}

__global__ void memprep_kernel(const float* __restrict__ decayp)
{
    long i = (long)blockIdx.x * 256 + threadIdx.x;
    if (i >= (long)BL * DD) return;
    long bl = i / DD;
    int l = (int)(bl % LL);
    float gamma = 1.f / (1.f + expf(-decayp[0]));
    float lg = logf(gamma);
    int tt = l % MC;
    float wkv = (l == 0) ? 0.f : g_out[i - DD];
    split2(wkv, g_wkh[i], g_wkl[i]);
    float rk = g_out[i] * expf((float)tt * lg);
    split2(rk, g_rkgh[i], g_rkgl[i]);
    g_vgw[i] = g_v[i] * expf((float)(MC - 1 - tt) * lg);
}

__global__ void wscan_kernel(const float* __restrict__ decayp)
{
    long i = (long)blockIdx.x * 256 + threadIdx.x;
    if (i >= (long)BB * DD * DD) return;
    long de = i % ((long)DD * DD);
    long b = i / ((long)DD * DD);
    float gamma = 1.f / (1.f + expf(-decayp[0]));
    float gmc = expf(256.f * logf(gamma));
    float w = 0.f;
    for (int c = 0; c < NM; c++) {
        long off = (b * NM + c) * (long)(DD * DD) + de;
        split2(w, g_Wsth[off], g_Wstl[off]);
        w = gmc * w + g_U[off];
    }
}

// ================= host launcher =================
template <typename T>
static T* symaddr(const void* s)
{
    void* p = nullptr;
    cudaGetSymbolAddress(&p, s);
    return (T*)p;
}

extern "C" void kernel_launch(void* const* d_in, const int* in_sizes, int n_in,
                              void* d_out, int out_size)
{
    const float* x = (const float*)d_in[0];
    const float* norm_w = (const float*)d_in[1];
    const float* w_in = (const float*)d_in[2];
    const float* conv_w = (const float*)d_in[3];
    const float* conv_b = (const float*)d_in[4];
    const float* A_log = (const float*)d_in[5];
    const float* dt_bias = (const float*)d_in[6];
    const float* D_skip = (const float*)d_in[7];
    const float* w_out = (const float*)d_in[8];
    const float* w_write = (const float*)d_in[9];
    const float* w_read = (const float*)d_in[10];
    const float* decay = (const float*)d_in[11];
    float* out = (float*)d_out;

    typedef __nv_bfloat16 bf;
    float* p_proj  = symaddr<float>(g_proj);
    float* p_out   = symaddr<float>(g_out);
    float* p_v     = symaddr<float>(g_v);
    float* p_vgw   = symaddr<float>(g_vgw);
    float* p_U     = symaddr<float>(g_U);
    float* p_reads = symaddr<float>(g_reads);
    bf *xnh = symaddr<bf>(g_xnh),   *xnl = symaddr<bf>(g_xnl);
    bf *winh = symaddr<bf>(g_winh), *winl = symaddr<bf>(g_winl);
    bf *Ygh = symaddr<bf>(g_Ygh),   *Ygl = symaddr<bf>(g_Ygl);
    bf *woh = symaddr<bf>(g_woh),   *wol = symaddr<bf>(g_wol);
    bf *outh = symaddr<bf>(g_outh), *outl = symaddr<bf>(g_outl);
    bf *wwh = symaddr<bf>(g_wwh),   *wwl = symaddr<bf>(g_wwl);
    bf *wrh = symaddr<bf>(g_wrh),   *wrl = symaddr<bf>(g_wrl);
    bf *wkh = symaddr<bf>(g_wkh),   *wkl = symaddr<bf>(g_wkl);
    bf *wkTh = symaddr<bf>(g_wkTh), *wkTl = symaddr<bf>(g_wkTl);
    bf *rkgh = symaddr<bf>(g_rkgh), *rkgl = symaddr<bf>(g_rkgl);
    bf *vgwTh = symaddr<bf>(g_vgwTh), *vgwTl = symaddr<bf>(g_vgwTl);
    bf *vTh = symaddr<bf>(g_vTh),   *vTl = symaddr<bf>(g_vTl);
    bf *Wsth = symaddr<bf>(g_Wsth), *Wstl = symaddr<bf>(g_Wstl);
    bf *Phh = symaddr<bf>(g_Ph),    *Pll = symaddr<bf>(g_Pl);
    bf *rdh = symaddr<bf>(g_rdh),   *rdl = symaddr<bf>(g_rdl);

    const int gsmem = 2 * STAGE_B;  // 81920
    cudaFuncSetAttribute(tgemm_kernel, cudaFuncAttributeMaxDynamicSharedMemorySize, gsmem);
    const int ysmem = (128 * 65 + 8448 + 64 * 65 + 256) * 4;
    cudaFuncSetAttribute(ssd_Y_kernel, cudaFuncAttributeMaxDynamicSharedMemorySize, ysmem);

    // weight splits
    splitk_kernel<<<(int)(((long)PROJ * DD + 255) / 256), 256>>>(w_in, winh, winl, (long)PROJ * DD);
    splitk_kernel<<<(int)(((long)DD * DI + 255) / 256), 256>>>(w_out, woh, wol, (long)DD * DI);
    splitk_kernel<<<(int)(((long)DD * DD + 255) / 256), 256>>>(w_write, wwh, wwl, (long)DD * DD);
    splitk_kernel<<<(int)(((long)DD * DD + 255) / 256), 256>>>(w_read, wrh, wrl, (long)DD * DD);

    // rmsnorm -> xn splits
    rmsnorm_kernel<<<BL, 256>>>(x, norm_w);

    // proj = xn @ w_in^T  [8192 x 8208 x 1024]
    tgemm_kernel<<<dim3((PROJ + 127) / 128, BL / 128, 1), 256, gsmem>>>(
        xnh, xnl, winh, winl, p_proj, nullptr, nullptr,
        PROJ, DD, DD, DD, PROJ, 0, 0, 0, EPI_STORE, nullptr, nullptr, nullptr, 0.f);

    conv_silu_kernel<<<(int)(((long)BL * DI + 255) / 256), 256>>>(conv_w, conv_b);
    cum_kernel<<<BB * HH * NC, 256>>>(dt_bias, A_log);
    ssd_T_kernel<<<BB * HH * NC, 256>>>();
    hscan_kernel<<<(int)(((long)BB * HH * HD * NN + 255) / 256), 256>>>();
    ssd_Y_kernel<<<BB * HH * NC * 4, 256, ysmem>>>(D_skip);

    // out = Yg @ w_out^T  (store fp32 + splits)
    tgemm_kernel<<<dim3(DD / 128, BL / 128, 1), 256, gsmem>>>(
        Ygh, Ygl, woh, wol, p_out, outh, outl,
        DD, DI, DI, DI, DD, 0, 0, 0, EPI_STORE_SPLIT, nullptr, nullptr, nullptr, 0.f);

    // v = out @ w_write^T
    tgemm_kernel<<<dim3(DD / 128, BL / 128, 1), 256, gsmem>>>(
        outh, outl, wwh, wwl, p_v, nullptr, nullptr,
        DD, DD, DD, DD, DD, 0, 0, 0, EPI_STORE, nullptr, nullptr, nullptr, 0.f);

    memprep_kernel<<<(int)(((long)BL * DD + 255) / 256), 256>>>(decay);
    tsplit_kernel<<<(int)(((long)BL * DD + 255) / 256), 256>>>(p_vgw, vgwTh, vgwTl, 0);
    tsplit_kernel<<<(int)(((long)BL * DD + 255) / 256), 256>>>(p_v, vTh, vTl, 0);
    tsplit_kernel<<<(int)(((long)BL * DD + 255) / 256), 256>>>(p_out, wkTh, wkTl, 1);

    // U[b,c,d,e] = sum_t vgwT[d,t]*wkT[e,t]
    tgemm_kernel<<<dim3(DD / 128, DD / 128, BB * NM), 256, gsmem>>>(
        vgwTh, vgwTl, wkTh, wkTl, p_U, nullptr, nullptr,
        DD, MC, MC, MC, DD,
        (long)DD * MC, (long)DD * MC, (long)DD * DD,
        EPI_STORE, nullptr, nullptr, nullptr, 0.f);

    wscan_kernel<<<(int)(((long)BB * DD * DD + 255) / 256), 256>>>(decay);

    // inter: reads = rkg @ Wst^T
    tgemm_kernel<<<dim3(DD / 128, MC / 128, BB * NM), 256, gsmem>>>(
        rkgh, rkgl, Wsth, Wstl, p_reads, nullptr, nullptr,
        DD, DD, DD, DD, DD,
        (long)MC * DD, (long)DD * DD, (long)MC * DD,
        EPI_STORE, nullptr, nullptr, nullptr, 0.f);

    // P = (out @ wk^T) * Mmem  -> split
    tgemm_kernel<<<dim3(MC / 128, MC / 128, BB * NM), 256, gsmem>>>(
        outh, outl, wkh, wkl, p_reads /*unused*/, Phh, Pll,
        MC, DD, DD, DD, MC,
        (long)MC * DD, (long)MC * DD, (long)MC * MC,
        EPI_MASK_SPLIT, nullptr, nullptr, decay, 0.f);

    // reads += P @ v  (B = vT)
    tgemm_kernel<<<dim3(DD / 128, MC / 128, BB * NM), 256, gsmem>>>(
        Phh, Pll, vTh, vTl, p_reads, nullptr, nullptr,
        DD, MC, MC, MC, DD,
        (long)MC * MC, (long)DD * MC, (long)MC * DD,
        EPI_ADD, nullptr, nullptr, nullptr, 0.f);

    splitk_kernel<<<(int)(((long)BL * DD + 255) / 256), 256>>>(p_reads, rdh, rdl, (long)BL * DD);

    // final = x + out + 0.5 * reads @ w_read^T
    tgemm_kernel<<<dim3(DD / 128, BL / 128, 1), 256, gsmem>>>(
        rdh, rdl, wrh, wrl, out, nullptr, nullptr,
        DD, DD, DD, DD, DD, 0, 0, 0,
        EPI_FINAL, x, p_out, nullptr, ALPHA);
}